// round 3
// baseline (speedup 1.0000x reference)
#include <cuda_runtime.h>
#include <math.h>

// Problem constants
#define B_SZ   32
#define C_IN   273
#define T_LEN  3000
#define O_OUT  270
#define KDIM   2048
#define NROWS  (B_SZ * C_IN)   // 8736

// GEMM tiling
#define BM 96
#define BN 128
#define BK 32
#define LDA 98    // padded leading dim for As[k][m]  (even -> 8B aligned pair loads, 2-way store conflicts max)
#define LDB 132   // padded leading dim for Bs[k][n]  (multiple of 4 -> 16B aligned float4)

// Scratch (static device globals: allocation-free)
__device__ float g_emb[(size_t)NROWS * KDIM];          // [8736][2048] fourier embedding
__device__ float g_w[(size_t)B_SZ * O_OUT * C_IN];     // [32][270][273] scores -> weights (in place)

// ---------------------------------------------------------------------------
// Packed fp32x2 helpers (sm_103a FFMA2 path)
// ---------------------------------------------------------------------------
__device__ __forceinline__ void ffma2(unsigned long long &d, unsigned long long a, unsigned long long b) {
    asm("fma.rn.f32x2 %0, %1, %2, %0;" : "+l"(d) : "l"(a), "l"(b));
}
__device__ __forceinline__ unsigned long long bcast2(float x) {
    unsigned long long r;
    asm("mov.b64 %0, {%1, %1};" : "=l"(r) : "f"(x));
    return r;
}
__device__ __forceinline__ void unpack2(unsigned long long v, float &lo, float &hi) {
    asm("mov.b64 {%0, %1}, %2;" : "=f"(lo), "=f"(hi) : "l"(v));
}

// ---------------------------------------------------------------------------
// Kernel 1: Fourier embedding. One warp per (b,c) row.
// Uses sin(ai+bj) = sin(ai)cos(bj)+cos(ai)sin(bj): 64 sincosf per row total.
// ---------------------------------------------------------------------------
__global__ void k_emb(const float* __restrict__ layout) {
    int warp = threadIdx.x >> 5;
    int lane = threadIdx.x & 31;
    int row  = blockIdx.x * 8 + warp;
    if (row >= NROWS) return;

    float x = layout[row * 2 + 0];
    float y = layout[row * 2 + 1];
    const float TWO_PI = 6.283185307179586476f;
    float pa = TWO_PI * ((x + 0.1f) * (1.0f / 1.2f));
    float pb = TWO_PI * ((y + 0.1f) * (1.0f / 1.2f));

    float sa, ca, sb, cb;
    sincosf(pa * (float)lane, &sa, &ca);   // lane = frequency index i
    sincosf(pb * (float)lane, &sb, &cb);   // lane = frequency index j

    float* dst = g_emb + (size_t)row * KDIM;
    #pragma unroll 4
    for (int i = 0; i < 32; i++) {
        float sai = __shfl_sync(0xffffffffu, sa, i);
        float cai = __shfl_sync(0xffffffffu, ca, i);
        // j = lane
        dst[i * 32 + lane]        = fmaf(sai, cb,  cai * sb);   // sin(a*i + b*j)
        dst[1024 + i * 32 + lane] = fmaf(cai, cb, -sai * sb);   // cos(a*i + b*j)
    }
}

// ---------------------------------------------------------------------------
// Kernel 2: scores GEMM.  A = heads [270 x 2048] (M=o), B = emb^T (N = row index rr).
// scores[b][o][c] = sum_d heads[o][d] * emb[rr][d],  rr = b*273 + c.
// Output written directly in [B][O][C] layout into g_w.
// ---------------------------------------------------------------------------
__global__ __launch_bounds__(256, 2) void k_gemm1(const float* __restrict__ heads) {
    __shared__ float As[BK * LDA];
    __shared__ float Bs[BK * LDB];

    int tid = threadIdx.x;
    int m0 = blockIdx.y * BM;
    int n0 = blockIdx.x * BN;
    int tx = tid & 15, ty = tid >> 4;
    int mloc = ty * 6, nloc = tx * 8;
    int lr  = tid >> 3;   // 0..31
    int lc4 = tid & 7;    // 0..7

    unsigned long long acc[3][8];
    #pragma unroll
    for (int i = 0; i < 3; i++)
        #pragma unroll
        for (int j = 0; j < 8; j++) acc[i][j] = 0ull;

    for (int k0 = 0; k0 < KDIM; k0 += BK) {
        // stage A tile (96 x 32) from heads, guarded on o
        float4 av[3];
        #pragma unroll
        for (int u = 0; u < 3; u++) {
            int o = m0 + lr + u * 32;
            if (o < O_OUT)
                av[u] = *reinterpret_cast<const float4*>(&heads[(size_t)o * KDIM + k0 + lc4 * 4]);
            else
                av[u] = make_float4(0.f, 0.f, 0.f, 0.f);
        }
        // stage B tile (128 rows x 32 k) from emb, guarded on rr
        float4 bv[4];
        #pragma unroll
        for (int u = 0; u < 4; u++) {
            int rr = n0 + lr + u * 32;
            if (rr < NROWS)
                bv[u] = *reinterpret_cast<const float4*>(&g_emb[(size_t)rr * KDIM + k0 + lc4 * 4]);
            else
                bv[u] = make_float4(0.f, 0.f, 0.f, 0.f);
        }
        __syncthreads();
        // transposed stores: As[k][m], Bs[k][n]
        #pragma unroll
        for (int u = 0; u < 3; u++) {
            int m = lr + u * 32;
            As[(lc4 * 4 + 0) * LDA + m] = av[u].x;
            As[(lc4 * 4 + 1) * LDA + m] = av[u].y;
            As[(lc4 * 4 + 2) * LDA + m] = av[u].z;
            As[(lc4 * 4 + 3) * LDA + m] = av[u].w;
        }
        #pragma unroll
        for (int u = 0; u < 4; u++) {
            int n = lr + u * 32;
            Bs[(lc4 * 4 + 0) * LDB + n] = bv[u].x;
            Bs[(lc4 * 4 + 1) * LDB + n] = bv[u].y;
            Bs[(lc4 * 4 + 2) * LDB + n] = bv[u].z;
            Bs[(lc4 * 4 + 3) * LDB + n] = bv[u].w;
        }
        __syncthreads();

        #pragma unroll 8
        for (int kk = 0; kk < BK; kk++) {
            const unsigned long long* ap =
                reinterpret_cast<const unsigned long long*>(&As[kk * LDA + mloc]);
            unsigned long long a0 = ap[0], a1 = ap[1], a2 = ap[2];
            float4 q0 = *reinterpret_cast<const float4*>(&Bs[kk * LDB + nloc]);
            float4 q1 = *reinterpret_cast<const float4*>(&Bs[kk * LDB + nloc + 4]);
            unsigned long long bb[8];
            bb[0] = bcast2(q0.x); bb[1] = bcast2(q0.y);
            bb[2] = bcast2(q0.z); bb[3] = bcast2(q0.w);
            bb[4] = bcast2(q1.x); bb[5] = bcast2(q1.y);
            bb[6] = bcast2(q1.z); bb[7] = bcast2(q1.w);
            #pragma unroll
            for (int j = 0; j < 8; j++) {
                ffma2(acc[0][j], a0, bb[j]);
                ffma2(acc[1][j], a1, bb[j]);
                ffma2(acc[2][j], a2, bb[j]);
            }
        }
    }

    // epilogue: scatter into [b][o][c] layout
    #pragma unroll
    for (int j = 0; j < 8; j++) {
        int rr = n0 + nloc + j;
        if (rr >= NROWS) continue;
        int bb_ = rr / C_IN;
        int cc  = rr - bb_ * C_IN;
        float* outp = g_w + (size_t)bb_ * O_OUT * C_IN + cc;
        #pragma unroll
        for (int i = 0; i < 3; i++) {
            float lo, hi;
            unpack2(acc[i][j], lo, hi);
            int o = m0 + mloc + 2 * i;
            if (o < O_OUT)     outp[(size_t)o * C_IN]       = lo;
            if (o + 1 < O_OUT) outp[(size_t)(o + 1) * C_IN] = hi;
        }
    }
}

// ---------------------------------------------------------------------------
// Kernel 3: in-place softmax over C for each (b,o) row of g_w. One warp/row.
// ---------------------------------------------------------------------------
__global__ void k_softmax() {
    int warp = threadIdx.x >> 5;
    int lane = threadIdx.x & 31;
    int row  = blockIdx.x * 8 + warp;
    if (row >= B_SZ * O_OUT) return;
    float* base = g_w + (size_t)row * C_IN;

    float v[9];
    float mx = -3.0e38f;
    #pragma unroll
    for (int it = 0; it < 9; it++) {
        int c = lane + it * 32;
        v[it] = (c < C_IN) ? base[c] : -3.0e38f;
        mx = fmaxf(mx, v[it]);
    }
    #pragma unroll
    for (int off = 16; off; off >>= 1)
        mx = fmaxf(mx, __shfl_xor_sync(0xffffffffu, mx, off));
    float s = 0.f;
    #pragma unroll
    for (int it = 0; it < 9; it++) {
        int c = lane + it * 32;
        float e = (c < C_IN) ? expf(v[it] - mx) : 0.f;
        v[it] = e; s += e;
    }
    #pragma unroll
    for (int off = 16; off; off >>= 1)
        s += __shfl_xor_sync(0xffffffffu, s, off);
    float inv = 1.f / s;
    #pragma unroll
    for (int it = 0; it < 9; it++) {
        int c = lane + it * 32;
        if (c < C_IN) base[c] = v[it] * inv;
    }
}

// ---------------------------------------------------------------------------
// Kernel 4: output GEMM. Per b:  out[o][t] = sum_c W[o][c] * brain[c][t].
// A = weights [270 x 273] (K=c), B = brain[b] [273 x 3000] (N=t contiguous).
// ---------------------------------------------------------------------------
__global__ __launch_bounds__(256, 2) void k_gemm2(const float* __restrict__ brain,
                                                  float* __restrict__ out) {
    __shared__ float As[BK * LDA];
    __shared__ float Bs[BK * LDB];

    int b = blockIdx.z;
    const float* Wb = g_w + (size_t)b * O_OUT * C_IN;
    const float* Bb = brain + (size_t)b * C_IN * T_LEN;
    float* Ob = out + (size_t)b * O_OUT * T_LEN;

    int tid = threadIdx.x;
    int m0 = blockIdx.y * BM;
    int n0 = blockIdx.x * BN;
    int tx = tid & 15, ty = tid >> 4;
    int mloc = ty * 6, nloc = tx * 8;
    int lr  = tid >> 3;   // 0..31
    int lc4 = tid & 7;    // 0..7
    int kq  = tid >> 5;   // 0..7
    int f4  = tid & 31;   // 0..31

    unsigned long long acc[3][8];
    #pragma unroll
    for (int i = 0; i < 3; i++)
        #pragma unroll
        for (int j = 0; j < 8; j++) acc[i][j] = 0ull;

    for (int k0 = 0; k0 < C_IN; k0 += BK) {   // 9 tiles, last ragged (k<273 guarded)
        // stage A tile (96 x 32) from weights (scalar, fully guarded)
        float av[3][4];
        #pragma unroll
        for (int u = 0; u < 3; u++) {
            int o = m0 + lr + u * 32;
            #pragma unroll
            for (int w = 0; w < 4; w++) {
                int k = k0 + lc4 * 4 + w;
                av[u][w] = (o < O_OUT && k < C_IN) ? Wb[(size_t)o * C_IN + k] : 0.f;
            }
        }
        // stage B tile (32 k x 128 t) from brain (float4, guarded)
        float4 bv[4];
        #pragma unroll
        for (int u = 0; u < 4; u++) {
            int k = k0 + kq + u * 8;
            int n = n0 + f4 * 4;
            if (k < C_IN && n < T_LEN)
                bv[u] = *reinterpret_cast<const float4*>(&Bb[(size_t)k * T_LEN + n]);
            else
                bv[u] = make_float4(0.f, 0.f, 0.f, 0.f);
        }
        __syncthreads();
        #pragma unroll
        for (int u = 0; u < 3; u++) {
            int m = lr + u * 32;
            #pragma unroll
            for (int w = 0; w < 4; w++)
                As[(lc4 * 4 + w) * LDA + m] = av[u][w];
        }
        #pragma unroll
        for (int u = 0; u < 4; u++)
            *reinterpret_cast<float4*>(&Bs[(kq + u * 8) * LDB + f4 * 4]) = bv[u];
        __syncthreads();

        #pragma unroll 8
        for (int kk = 0; kk < BK; kk++) {
            const unsigned long long* ap =
                reinterpret_cast<const unsigned long long*>(&As[kk * LDA + mloc]);
            unsigned long long a0 = ap[0], a1 = ap[1], a2 = ap[2];
            float4 q0 = *reinterpret_cast<const float4*>(&Bs[kk * LDB + nloc]);
            float4 q1 = *reinterpret_cast<const float4*>(&Bs[kk * LDB + nloc + 4]);
            unsigned long long bb[8];
            bb[0] = bcast2(q0.x); bb[1] = bcast2(q0.y);
            bb[2] = bcast2(q0.z); bb[3] = bcast2(q0.w);
            bb[4] = bcast2(q1.x); bb[5] = bcast2(q1.y);
            bb[6] = bcast2(q1.z); bb[7] = bcast2(q1.w);
            #pragma unroll
            for (int j = 0; j < 8; j++) {
                ffma2(acc[0][j], a0, bb[j]);
                ffma2(acc[1][j], a1, bb[j]);
                ffma2(acc[2][j], a2, bb[j]);
            }
        }
    }

    #pragma unroll
    for (int j = 0; j < 8; j++) {
        int t = n0 + nloc + j;
        if (t >= T_LEN) continue;
        #pragma unroll
        for (int i = 0; i < 3; i++) {
            float lo, hi;
            unpack2(acc[i][j], lo, hi);
            int o = m0 + mloc + 2 * i;
            if (o < O_OUT)     Ob[(size_t)o * T_LEN + t]       = lo;
            if (o + 1 < O_OUT) Ob[(size_t)(o + 1) * T_LEN + t] = hi;
        }
    }
}

// ---------------------------------------------------------------------------
// Launch: emb -> scores GEMM -> softmax -> output GEMM (all on capture stream)
// ---------------------------------------------------------------------------
extern "C" void kernel_launch(void* const* d_in, const int* in_sizes, int n_in,
                              void* d_out, int out_size) {
    const float* brain  = (const float*)d_in[0];   // [32, 273, 3000]
    const float* layout = (const float*)d_in[1];   // [32, 273, 2]
    const float* heads  = (const float*)d_in[2];   // [270, 2048]
    float* out = (float*)d_out;                    // [32, 270, 3000]

    k_emb<<<NROWS / 8, 256>>>(layout);

    dim3 g1((NROWS + BN - 1) / BN, (O_OUT + BM - 1) / BM);      // 69 x 3
    k_gemm1<<<g1, 256>>>(heads);

    k_softmax<<<(B_SZ * O_OUT + 7) / 8, 256>>>();

    dim3 g2((T_LEN + BN - 1) / BN, (O_OUT + BM - 1) / BM, B_SZ); // 24 x 3 x 32
    k_gemm2<<<g2, 256>>>(brain, out);
}

// round 5
// speedup vs baseline: 2.1229x; 2.1229x over previous
#include <cuda_runtime.h>
#include <cuda_bf16.h>
#include <math.h>
#include <stdint.h>

// ---------------------------------------------------------------- constants
#define B_SZ   32
#define C_IN   273
#define T_LEN  3000
#define O_OUT  270
#define KDIM   2048
#define NROWS  (B_SZ * C_IN)   // 8736
#define EROWS  8960            // 70*128 pad (69 tiles used)
#define ORPAD  384             // 3*128
#define TPAD   3072            // 24*128
#define K2PAD  288             // 9*32 (K=273 padded)
#define LDT    40              // smem tile leading dim (bf16 elems) -> 80B rows

// ---------------------------------------------------------------- scratch
__device__ float g_w[(size_t)B_SZ * O_OUT * C_IN];                 // scores/weights fp32
__device__ __nv_bfloat16 g_Eh[(size_t)EROWS * KDIM];               // emb hi
__device__ __nv_bfloat16 g_El[(size_t)EROWS * KDIM];               // emb lo
__device__ __nv_bfloat16 g_Hh[(size_t)ORPAD * KDIM];               // heads hi
__device__ __nv_bfloat16 g_Hl[(size_t)ORPAD * KDIM];               // heads lo
__device__ __nv_bfloat16 g_Bth[(size_t)B_SZ * TPAD * K2PAD];       // brain^T hi [b][t][c]
__device__ __nv_bfloat16 g_Btl[(size_t)B_SZ * TPAD * K2PAD];       // brain^T lo
__device__ __nv_bfloat16 g_Wh[(size_t)B_SZ * ORPAD * K2PAD];       // weights hi [b][o][c]
__device__ __nv_bfloat16 g_Wl[(size_t)B_SZ * ORPAD * K2PAD];       // weights lo

// ---------------------------------------------------------------- helpers
__device__ __forceinline__ uint32_t smem_u32(const void* p) {
    uint32_t a;
    asm("{ .reg .u64 t; cvta.to.shared.u64 t, %1; cvt.u32.u64 %0, t; }" : "=r"(a) : "l"(p));
    return a;
}
__device__ __forceinline__ void ldm_x4(uint32_t* r, uint32_t addr) {
    asm volatile("ldmatrix.sync.aligned.m8n8.x4.shared.b16 {%0,%1,%2,%3}, [%4];"
        : "=r"(r[0]), "=r"(r[1]), "=r"(r[2]), "=r"(r[3]) : "r"(addr));
}
__device__ __forceinline__ void ldm_x2(uint32_t* r, uint32_t addr) {
    asm volatile("ldmatrix.sync.aligned.m8n8.x2.shared.b16 {%0,%1}, [%2];"
        : "=r"(r[0]), "=r"(r[1]) : "r"(addr));
}
__device__ __forceinline__ void mma16816(float* c, const uint32_t* a, const uint32_t* b) {
    asm volatile("mma.sync.aligned.m16n8k16.row.col.f32.bf16.bf16.f32 "
        "{%0,%1,%2,%3}, {%4,%5,%6,%7}, {%8,%9}, {%0,%1,%2,%3};"
        : "+f"(c[0]), "+f"(c[1]), "+f"(c[2]), "+f"(c[3])
        : "r"(a[0]), "r"(a[1]), "r"(a[2]), "r"(a[3]), "r"(b[0]), "r"(b[1]));
}
__device__ __forceinline__ void split_bf16(float v, __nv_bfloat16& h, __nv_bfloat16& l) {
    h = __float2bfloat16(v);
    l = __float2bfloat16(v - __bfloat162float(h));
}

// ---------------------------------------------------------------- fourier emb
__global__ void k_emb(const float* __restrict__ layout) {
    int warp = threadIdx.x >> 5, lane = threadIdx.x & 31;
    int row = blockIdx.x * 8 + warp;
    if (row >= NROWS) return;
    float x = layout[row * 2 + 0], y = layout[row * 2 + 1];
    const float TWO_PI = 6.283185307179586476f;
    float pa = TWO_PI * ((x + 0.1f) * (1.0f / 1.2f));
    float pb = TWO_PI * ((y + 0.1f) * (1.0f / 1.2f));
    float sa, ca, sb, cb;
    sincosf(pa * (float)lane, &sa, &ca);
    sincosf(pb * (float)lane, &sb, &cb);
    size_t base = (size_t)row * KDIM;
    #pragma unroll 4
    for (int i = 0; i < 32; i++) {
        float sai = __shfl_sync(0xffffffffu, sa, i);
        float cai = __shfl_sync(0xffffffffu, ca, i);
        float vs = fmaf(sai, cb,  cai * sb);   // sin
        float vc = fmaf(cai, cb, -sai * sb);   // cos
        __nv_bfloat16 h, l;
        split_bf16(vs, h, l);
        g_Eh[base + i * 32 + lane] = h;  g_El[base + i * 32 + lane] = l;
        split_bf16(vc, h, l);
        g_Eh[base + 1024 + i * 32 + lane] = h;  g_El[base + 1024 + i * 32 + lane] = l;
    }
}

// ---------------------------------------------------------------- conversions
__global__ void k_conv_heads(const float* __restrict__ heads) {
    int idx = blockIdx.x * 256 + threadIdx.x;
    if (idx >= O_OUT * KDIM) return;
    __nv_bfloat16 h, l;
    split_bf16(heads[idx], h, l);
    g_Hh[idx] = h; g_Hl[idx] = l;
}

__global__ void k_conv_brain(const float* __restrict__ brain) {
    __shared__ float tile[32][33];
    int b = blockIdx.z;
    int c0 = blockIdx.y * 32, t0 = blockIdx.x * 32;
    int tx = threadIdx.x, ty = threadIdx.y;   // block (32,8)
    const float* src = brain + (size_t)b * C_IN * T_LEN;
    #pragma unroll
    for (int u = 0; u < 4; u++) {
        int c = c0 + ty + u * 8, t = t0 + tx;
        tile[ty + u * 8][tx] = (c < C_IN && t < T_LEN) ? src[(size_t)c * T_LEN + t] : 0.f;
    }
    __syncthreads();
    #pragma unroll
    for (int u = 0; u < 4; u++) {
        int t = t0 + ty + u * 8, c = c0 + tx;   // padded bounds: t<3072, c<288
        __nv_bfloat16 h, l;
        split_bf16(tile[tx][ty + u * 8], h, l);
        size_t di = ((size_t)b * TPAD + t) * K2PAD + c;
        g_Bth[di] = h; g_Btl[di] = l;
    }
}

__global__ void k_conv_w() {
    int idx = blockIdx.x * 256 + threadIdx.x;
    if (idx >= B_SZ * O_OUT * C_IN) return;
    int c = idx % C_IN; int rest = idx / C_IN;
    int o = rest % O_OUT; int b = rest / O_OUT;
    __nv_bfloat16 h, l;
    split_bf16(g_w[idx], h, l);
    size_t di = ((size_t)b * ORPAD + o) * K2PAD + c;
    g_Wh[di] = h; g_Wl[di] = l;
}

// ---------------------------------------------------------------- softmax
__global__ void k_softmax() {
    int warp = threadIdx.x >> 5, lane = threadIdx.x & 31;
    int row = blockIdx.x * 8 + warp;
    if (row >= B_SZ * O_OUT) return;
    float* base = g_w + (size_t)row * C_IN;
    float v[9];
    float mx = -3.0e38f;
    #pragma unroll
    for (int it = 0; it < 9; it++) {
        int c = lane + it * 32;
        v[it] = (c < C_IN) ? base[c] : -3.0e38f;
        mx = fmaxf(mx, v[it]);
    }
    #pragma unroll
    for (int off = 16; off; off >>= 1)
        mx = fmaxf(mx, __shfl_xor_sync(0xffffffffu, mx, off));
    float s = 0.f;
    #pragma unroll
    for (int it = 0; it < 9; it++) {
        int c = lane + it * 32;
        float e = (c < C_IN) ? expf(v[it] - mx) : 0.f;
        v[it] = e; s += e;
    }
    #pragma unroll
    for (int off = 16; off; off >>= 1)
        s += __shfl_xor_sync(0xffffffffu, s, off);
    float inv = 1.f / s;
    #pragma unroll
    for (int it = 0; it < 9; it++) {
        int c = lane + it * 32;
        if (c < C_IN) base[c] = v[it] * inv;
    }
}

// ---------------------------------------------------------------- GEMM (mma.sync split-bf16)
// Block tile 128x128, BK=32, 8 warps (2m x 4n), warp tile 64x32 = 4x4 m16n8k16.
// Operands K-major, fully padded -> no guards in mainloop.
// MODE 0: gemm1 (emb x heads -> scores into g_w, scattered [b][o][c])
// MODE 1: gemm2 (brainT x weights -> out [b][o][t])
template<int MODE, int KCHUNKS>
__global__ __launch_bounds__(256, 2) void k_gemm_mma(float* __restrict__ outp) {
    __shared__ __align__(16) __nv_bfloat16 sAh[128 * LDT];
    __shared__ __align__(16) __nv_bfloat16 sAl[128 * LDT];
    __shared__ __align__(16) __nv_bfloat16 sBh[128 * LDT];
    __shared__ __align__(16) __nv_bfloat16 sBl[128 * LDT];

    const int tid = threadIdx.x;
    const int lane = tid & 31, wid = tid >> 5;
    const int warp_m = wid >> 2, warp_n = wid & 3;

    // operand pointers + leading dims
    const __nv_bfloat16 *Ah, *Al, *Bh, *Bl;
    int lda, ldb, m0, n0, bb = 0;
    if (MODE == 0) {
        m0 = blockIdx.x * 128;  n0 = blockIdx.y * 128;
        lda = KDIM; ldb = KDIM;
        Ah = g_Eh + (size_t)m0 * KDIM;  Al = g_El + (size_t)m0 * KDIM;
        Bh = g_Hh + (size_t)n0 * KDIM;  Bl = g_Hl + (size_t)n0 * KDIM;
    } else {
        bb = blockIdx.z;
        m0 = blockIdx.x * 128;  n0 = blockIdx.y * 128;
        lda = K2PAD; ldb = K2PAD;
        Ah = g_Bth + ((size_t)bb * TPAD + m0) * K2PAD;
        Al = g_Btl + ((size_t)bb * TPAD + m0) * K2PAD;
        Bh = g_Wh + ((size_t)bb * ORPAD + n0) * K2PAD;
        Bl = g_Wl + ((size_t)bb * ORPAD + n0) * K2PAD;
    }

    float acc[4][4][4];
    #pragma unroll
    for (int i = 0; i < 4; i++)
        #pragma unroll
        for (int j = 0; j < 4; j++)
            #pragma unroll
            for (int q = 0; q < 4; q++) acc[i][j][q] = 0.f;

    // global->smem staging indices: 2 iters of (row, seg) per tile
    const int gr = tid >> 2;          // 0..63
    const int gs = tid & 3;           // 0..3 (16B seg)

    // ldmatrix base byte-offsets (per mi/ni add; per ks add 32B)
    const int a_row = warp_m * 64 + (lane & 15);
    const int a_col = (lane >> 4) * 8;
    const int b_row = warp_n * 32 + (lane & 7);
    const int b_col = ((lane >> 3) & 1) * 8;
    uint32_t pAh = smem_u32(sAh) + (a_row * LDT + a_col) * 2;
    uint32_t pAl = smem_u32(sAl) + (a_row * LDT + a_col) * 2;
    uint32_t pBh = smem_u32(sBh) + (b_row * LDT + b_col) * 2;
    uint32_t pBl = smem_u32(sBl) + (b_row * LDT + b_col) * 2;

    for (int kc = 0; kc < KCHUNKS; kc++) {
        const int k0 = kc * 32;
        // load 16B x 2 per tile per thread
        uint4 vah0 = *reinterpret_cast<const uint4*>(Ah + (size_t)gr * lda + k0 + gs * 8);
        uint4 vah1 = *reinterpret_cast<const uint4*>(Ah + (size_t)(gr + 64) * lda + k0 + gs * 8);
        uint4 val0 = *reinterpret_cast<const uint4*>(Al + (size_t)gr * lda + k0 + gs * 8);
        uint4 val1 = *reinterpret_cast<const uint4*>(Al + (size_t)(gr + 64) * lda + k0 + gs * 8);
        uint4 vbh0 = *reinterpret_cast<const uint4*>(Bh + (size_t)gr * ldb + k0 + gs * 8);
        uint4 vbh1 = *reinterpret_cast<const uint4*>(Bh + (size_t)(gr + 64) * ldb + k0 + gs * 8);
        uint4 vbl0 = *reinterpret_cast<const uint4*>(Bl + (size_t)gr * ldb + k0 + gs * 8);
        uint4 vbl1 = *reinterpret_cast<const uint4*>(Bl + (size_t)(gr + 64) * ldb + k0 + gs * 8);
        __syncthreads();
        *reinterpret_cast<uint4*>(&sAh[gr * LDT + gs * 8]) = vah0;
        *reinterpret_cast<uint4*>(&sAh[(gr + 64) * LDT + gs * 8]) = vah1;
        *reinterpret_cast<uint4*>(&sAl[gr * LDT + gs * 8]) = val0;
        *reinterpret_cast<uint4*>(&sAl[(gr + 64) * LDT + gs * 8]) = val1;
        *reinterpret_cast<uint4*>(&sBh[gr * LDT + gs * 8]) = vbh0;
        *reinterpret_cast<uint4*>(&sBh[(gr + 64) * LDT + gs * 8]) = vbh1;
        *reinterpret_cast<uint4*>(&sBl[gr * LDT + gs * 8]) = vbl0;
        *reinterpret_cast<uint4*>(&sBl[(gr + 64) * LDT + gs * 8]) = vbl1;
        __syncthreads();

        #pragma unroll
        for (int ks = 0; ks < 2; ks++) {
            const uint32_t ko = ks * 32;   // 16 elems * 2B
            uint32_t bh[4][2], bl[4][2], af[4][4];
            #pragma unroll
            for (int ni = 0; ni < 4; ni++)
                ldm_x2(bh[ni], pBh + ni * 8 * LDT * 2 + ko);
            #pragma unroll
            for (int mi = 0; mi < 4; mi++)
                ldm_x4(af[mi], pAh + mi * 16 * LDT * 2 + ko);
            #pragma unroll
            for (int mi = 0; mi < 4; mi++)
                #pragma unroll
                for (int ni = 0; ni < 4; ni++)
                    mma16816(acc[mi][ni], af[mi], bh[ni]);      // Ah*Bh
            #pragma unroll
            for (int ni = 0; ni < 4; ni++)
                ldm_x2(bl[ni], pBl + ni * 8 * LDT * 2 + ko);
            #pragma unroll
            for (int mi = 0; mi < 4; mi++)
                #pragma unroll
                for (int ni = 0; ni < 4; ni++)
                    mma16816(acc[mi][ni], af[mi], bl[ni]);      // Ah*Bl
            #pragma unroll
            for (int mi = 0; mi < 4; mi++)
                ldm_x4(af[mi], pAl + mi * 16 * LDT * 2 + ko);   // reuse regs
            #pragma unroll
            for (int mi = 0; mi < 4; mi++)
                #pragma unroll
                for (int ni = 0; ni < 4; ni++)
                    mma16816(acc[mi][ni], af[mi], bh[ni]);      // Al*Bh
        }
    }

    // epilogue
    const int erow = lane >> 2;
    const int ecol = (lane & 3) * 2;
    #pragma unroll
    for (int mi = 0; mi < 4; mi++) {
        #pragma unroll
        for (int ni = 0; ni < 4; ni++) {
            #pragma unroll
            for (int q = 0; q < 4; q++) {
                int gm = m0 + warp_m * 64 + mi * 16 + erow + (q >> 1) * 8;
                int gn = n0 + warp_n * 32 + ni * 8 + ecol + (q & 1);
                if (MODE == 0) {
                    if (gm < NROWS && gn < O_OUT) {
                        int b = gm / C_IN, c = gm - (gm / C_IN) * C_IN;
                        g_w[((size_t)b * O_OUT + gn) * C_IN + c] = acc[mi][ni][q];
                    }
                } else {
                    if (gm < T_LEN && gn < O_OUT)
                        outp[((size_t)bb * O_OUT + gn) * T_LEN + gm] = acc[mi][ni][q];
                }
            }
        }
    }
}

// ---------------------------------------------------------------- launch
extern "C" void kernel_launch(void* const* d_in, const int* in_sizes, int n_in,
                              void* d_out, int out_size) {
    const float* brain  = (const float*)d_in[0];   // [32, 273, 3000]
    const float* layout = (const float*)d_in[1];   // [32, 273, 2]
    const float* heads  = (const float*)d_in[2];   // [270, 2048]
    float* out = (float*)d_out;                    // [32, 270, 3000]

    k_emb<<<NROWS / 8, 256>>>(layout);
    k_conv_heads<<<(O_OUT * KDIM + 255) / 256, 256>>>(heads);
    k_conv_brain<<<dim3(94, 9, B_SZ), dim3(32, 8)>>>(brain);

    k_gemm_mma<0, KDIM / 32><<<dim3(69, 3), 256>>>(nullptr);      // scores

    k_softmax<<<(B_SZ * O_OUT + 7) / 8, 256>>>();
    k_conv_w<<<(B_SZ * O_OUT * C_IN + 255) / 256, 256>>>();

    k_gemm_mma<1, K2PAD / 32><<<dim3(24, 3, B_SZ), 256>>>(out);   // output
}

// round 6
// speedup vs baseline: 2.4472x; 1.1528x over previous
#include <cuda_runtime.h>
#include <cuda_bf16.h>
#include <math.h>
#include <stdint.h>

// ---------------------------------------------------------------- constants
#define B_SZ   32
#define C_IN   273
#define T_LEN  3000
#define O_OUT  270
#define KDIM   2048
#define NROWS  (B_SZ * C_IN)   // 8736
#define EROWS  8960            // 70*128 pad
#define ORPAD  288             // 3*96  (N padding for o)
#define TPAD   3072            // 24*128
#define K2PAD  288             // 9*32  (K=273 padded)
#define LDT    40              // smem leading dim (bf16) -> 80B rows

// smem stage layout (bytes)
#define STG_A      10240       // 128 x LDT x 2
#define STG_B      7680        // 96  x LDT x 2
#define OFF_AL     10240
#define OFF_BH     20480
#define OFF_BL     28160
#define STAGE_BYTES 35840
#define SMEM_TOTAL (2 * STAGE_BYTES)   // 71680

// ---------------------------------------------------------------- scratch
__device__ float g_w[(size_t)B_SZ * O_OUT * C_IN];                 // scores fp32
__device__ __nv_bfloat16 g_Eh[(size_t)EROWS * KDIM];               // emb hi
__device__ __nv_bfloat16 g_El[(size_t)EROWS * KDIM];               // emb lo
__device__ __nv_bfloat16 g_Hh[(size_t)ORPAD * KDIM];               // heads hi
__device__ __nv_bfloat16 g_Hl[(size_t)ORPAD * KDIM];               // heads lo
__device__ __nv_bfloat16 g_Bth[(size_t)B_SZ * TPAD * K2PAD];       // brain^T hi [b][t][c]
__device__ __nv_bfloat16 g_Btl[(size_t)B_SZ * TPAD * K2PAD];       // brain^T lo
__device__ __nv_bfloat16 g_Wh[(size_t)B_SZ * ORPAD * K2PAD];       // weights hi [b][o][c]
__device__ __nv_bfloat16 g_Wl[(size_t)B_SZ * ORPAD * K2PAD];       // weights lo

// ---------------------------------------------------------------- helpers
__device__ __forceinline__ uint32_t smem_u32(const void* p) {
    uint32_t a;
    asm("{ .reg .u64 t; cvta.to.shared.u64 t, %1; cvt.u32.u64 %0, t; }" : "=r"(a) : "l"(p));
    return a;
}
__device__ __forceinline__ void cp_async16(uint32_t dst, const void* src) {
    asm volatile("cp.async.cg.shared.global [%0], [%1], 16;" :: "r"(dst), "l"(src));
}
#define CP_COMMIT() asm volatile("cp.async.commit_group;" ::: "memory")
#define CP_WAIT(n)  asm volatile("cp.async.wait_group %0;" :: "n"(n) : "memory")

__device__ __forceinline__ void ldm_x4(uint32_t* r, uint32_t addr) {
    asm volatile("ldmatrix.sync.aligned.m8n8.x4.shared.b16 {%0,%1,%2,%3}, [%4];"
        : "=r"(r[0]), "=r"(r[1]), "=r"(r[2]), "=r"(r[3]) : "r"(addr));
}
__device__ __forceinline__ void ldm_x2(uint32_t* r, uint32_t addr) {
    asm volatile("ldmatrix.sync.aligned.m8n8.x2.shared.b16 {%0,%1}, [%2];"
        : "=r"(r[0]), "=r"(r[1]) : "r"(addr));
}
__device__ __forceinline__ void mma16816(float* c, const uint32_t* a, const uint32_t* b) {
    asm volatile("mma.sync.aligned.m16n8k16.row.col.f32.bf16.bf16.f32 "
        "{%0,%1,%2,%3}, {%4,%5,%6,%7}, {%8,%9}, {%0,%1,%2,%3};"
        : "+f"(c[0]), "+f"(c[1]), "+f"(c[2]), "+f"(c[3])
        : "r"(a[0]), "r"(a[1]), "r"(a[2]), "r"(a[3]), "r"(b[0]), "r"(b[1]));
}
__device__ __forceinline__ void split_bf16(float v, __nv_bfloat16& h, __nv_bfloat16& l) {
    h = __float2bfloat16(v);
    l = __float2bfloat16(v - __bfloat162float(h));
}

// ---------------------------------------------------------------- fourier emb
__global__ void k_emb(const float* __restrict__ layout) {
    int warp = threadIdx.x >> 5, lane = threadIdx.x & 31;
    int row = blockIdx.x * 8 + warp;
    if (row >= NROWS) return;
    float x = layout[row * 2 + 0], y = layout[row * 2 + 1];
    const float TWO_PI = 6.283185307179586476f;
    float pa = TWO_PI * ((x + 0.1f) * (1.0f / 1.2f));
    float pb = TWO_PI * ((y + 0.1f) * (1.0f / 1.2f));
    float sa, ca, sb, cb;
    sincosf(pa * (float)lane, &sa, &ca);
    sincosf(pb * (float)lane, &sb, &cb);
    size_t base = (size_t)row * KDIM;
    #pragma unroll 4
    for (int i = 0; i < 32; i++) {
        float sai = __shfl_sync(0xffffffffu, sa, i);
        float cai = __shfl_sync(0xffffffffu, ca, i);
        float vs = fmaf(sai, cb,  cai * sb);
        float vc = fmaf(cai, cb, -sai * sb);
        __nv_bfloat16 h, l;
        split_bf16(vs, h, l);
        g_Eh[base + i * 32 + lane] = h;  g_El[base + i * 32 + lane] = l;
        split_bf16(vc, h, l);
        g_Eh[base + 1024 + i * 32 + lane] = h;  g_El[base + 1024 + i * 32 + lane] = l;
    }
}

// ---------------------------------------------------------------- conversions
__global__ void k_conv_heads(const float* __restrict__ heads) {
    int idx = blockIdx.x * 256 + threadIdx.x;
    if (idx >= O_OUT * KDIM) return;
    __nv_bfloat16 h, l;
    split_bf16(heads[idx], h, l);
    g_Hh[idx] = h; g_Hl[idx] = l;
}

__global__ void k_conv_brain(const float* __restrict__ brain) {
    __shared__ float tile[32][33];
    int b = blockIdx.z;
    int c0 = blockIdx.y * 32, t0 = blockIdx.x * 32;
    int tx = threadIdx.x, ty = threadIdx.y;   // block (32,8)
    const float* src = brain + (size_t)b * C_IN * T_LEN;
    #pragma unroll
    for (int u = 0; u < 4; u++) {
        int c = c0 + ty + u * 8, t = t0 + tx;
        tile[ty + u * 8][tx] = (c < C_IN && t < T_LEN) ? src[(size_t)c * T_LEN + t] : 0.f;
    }
    __syncthreads();
    #pragma unroll
    for (int u = 0; u < 4; u++) {
        int t = t0 + ty + u * 8, c = c0 + tx;   // padded bounds: t<3072, c<288
        __nv_bfloat16 h, l;
        split_bf16(tile[tx][ty + u * 8], h, l);
        size_t di = ((size_t)b * TPAD + t) * K2PAD + c;
        g_Bth[di] = h; g_Btl[di] = l;
    }
}

// ---------------------------------------------------------------- softmax (+ fused bf16 split)
__global__ void k_softmax() {
    int warp = threadIdx.x >> 5, lane = threadIdx.x & 31;
    int row = blockIdx.x * 8 + warp;
    if (row >= B_SZ * O_OUT) return;
    int b = row / O_OUT, o = row - b * O_OUT;
    const float* base = g_w + (size_t)row * C_IN;
    float v[9];
    float mx = -3.0e38f;
    #pragma unroll
    for (int it = 0; it < 9; it++) {
        int c = lane + it * 32;
        v[it] = (c < C_IN) ? base[c] : -3.0e38f;
        mx = fmaxf(mx, v[it]);
    }
    #pragma unroll
    for (int off = 16; off; off >>= 1)
        mx = fmaxf(mx, __shfl_xor_sync(0xffffffffu, mx, off));
    float s = 0.f;
    #pragma unroll
    for (int it = 0; it < 9; it++) {
        int c = lane + it * 32;
        float e = (c < C_IN) ? expf(v[it] - mx) : 0.f;
        v[it] = e; s += e;
    }
    #pragma unroll
    for (int off = 16; off; off >>= 1)
        s += __shfl_xor_sync(0xffffffffu, s, off);
    float inv = 1.f / s;
    __nv_bfloat16* wh = g_Wh + ((size_t)b * ORPAD + o) * K2PAD;
    __nv_bfloat16* wl = g_Wl + ((size_t)b * ORPAD + o) * K2PAD;
    #pragma unroll
    for (int it = 0; it < 9; it++) {
        int c = lane + it * 32;
        if (c < C_IN) {
            __nv_bfloat16 h, l;
            split_bf16(v[it] * inv, h, l);
            wh[c] = h; wl[c] = l;
        }
    }
}

// ---------------------------------------------------------------- GEMM
// Block 128(m) x 96(n), BK=32, 8 warps (2m x 4n), warp 64x24 = 4x3 m16n8k16.
// split-bf16 3-MMA fp32 emulation. cp.async double-buffered.
// MODE 0: scores = emb x heads  -> g_w [b][o][c]
// MODE 1: out    = brainT x W   -> out [b][o][t]
__device__ __forceinline__ void stage_loads(uint32_t sbase,
        const __nv_bfloat16* __restrict__ Ah, const __nv_bfloat16* __restrict__ Al, int lda,
        const __nv_bfloat16* __restrict__ Bh, const __nv_bfloat16* __restrict__ Bl, int ldb,
        int k0, int tid) {
    #pragma unroll
    for (int u = 0; u < 2; u++) {
        int idx = u * 256 + tid;
        int row = idx >> 2, seg = idx & 3;
        uint32_t d = sbase + (row * LDT + seg * 8) * 2;
        cp_async16(d,         Ah + (size_t)row * lda + k0 + seg * 8);
        cp_async16(d + OFF_AL, Al + (size_t)row * lda + k0 + seg * 8);
    }
    #pragma unroll
    for (int u = 0; u < 2; u++) {
        int idx = u * 256 + tid;
        if (idx < 384) {
            int row = idx >> 2, seg = idx & 3;
            uint32_t d = sbase + OFF_BH + (row * LDT + seg * 8) * 2;
            cp_async16(d,                 Bh + (size_t)row * ldb + k0 + seg * 8);
            cp_async16(d + (OFF_BL - OFF_BH), Bl + (size_t)row * ldb + k0 + seg * 8);
        }
    }
}

template<int MODE, int KCHUNKS>
__global__ __launch_bounds__(256, 2) void k_gemm_mma(float* __restrict__ outp) {
    extern __shared__ __align__(16) char dsm[];
    const uint32_t sb = smem_u32(dsm);

    const int tid = threadIdx.x;
    const int lane = tid & 31, wid = tid >> 5;
    const int warp_m = wid >> 2, warp_n = wid & 3;

    const __nv_bfloat16 *Ah, *Al, *Bh, *Bl;
    int lda, ldb, m0, n0, bb = 0;
    if (MODE == 0) {
        m0 = blockIdx.x * 128;  n0 = blockIdx.y * 96;
        lda = KDIM; ldb = KDIM;
        Ah = g_Eh + (size_t)m0 * KDIM;  Al = g_El + (size_t)m0 * KDIM;
        Bh = g_Hh + (size_t)n0 * KDIM;  Bl = g_Hl + (size_t)n0 * KDIM;
    } else {
        bb = blockIdx.z;
        m0 = blockIdx.x * 128;  n0 = blockIdx.y * 96;
        lda = K2PAD; ldb = K2PAD;
        Ah = g_Bth + ((size_t)bb * TPAD + m0) * K2PAD;
        Al = g_Btl + ((size_t)bb * TPAD + m0) * K2PAD;
        Bh = g_Wh + ((size_t)bb * ORPAD + n0) * K2PAD;
        Bl = g_Wl + ((size_t)bb * ORPAD + n0) * K2PAD;
    }

    float acc[4][3][4];
    #pragma unroll
    for (int i = 0; i < 4; i++)
        #pragma unroll
        for (int j = 0; j < 3; j++)
            #pragma unroll
            for (int q = 0; q < 4; q++) acc[i][j][q] = 0.f;

    // ldmatrix base byte-offsets within a stage
    const int a_row = warp_m * 64 + (lane & 15);
    const int a_col = (lane >> 4) * 8;
    const int b_row = warp_n * 24 + (lane & 7);
    const int b_col = ((lane >> 3) & 1) * 8;
    const uint32_t aoff = (a_row * LDT + a_col) * 2;
    const uint32_t boff = (b_row * LDT + b_col) * 2;

    // prologue
    stage_loads(sb, Ah, Al, lda, Bh, Bl, ldb, 0, tid);
    CP_COMMIT();

    for (int kc = 0; kc < KCHUNKS; kc++) {
        const uint32_t stg = sb + (uint32_t)(kc & 1) * STAGE_BYTES;
        if (kc + 1 < KCHUNKS) {
            stage_loads(sb + (uint32_t)((kc + 1) & 1) * STAGE_BYTES,
                        Ah, Al, lda, Bh, Bl, ldb, (kc + 1) * 32, tid);
            CP_COMMIT();
            CP_WAIT(1);
        } else {
            CP_WAIT(0);
        }
        __syncthreads();

        const uint32_t pAh = stg + aoff;
        const uint32_t pAl = stg + OFF_AL + aoff;
        const uint32_t pBh = stg + OFF_BH + boff;
        const uint32_t pBl = stg + OFF_BL + boff;
        #pragma unroll
        for (int ks = 0; ks < 2; ks++) {
            const uint32_t ko = ks * 32;   // 16 bf16 = 32 B
            uint32_t bh[3][2], bl[3][2], af[4][4];
            #pragma unroll
            for (int ni = 0; ni < 3; ni++)
                ldm_x2(bh[ni], pBh + ni * 8 * LDT * 2 + ko);
            #pragma unroll
            for (int mi = 0; mi < 4; mi++)
                ldm_x4(af[mi], pAh + mi * 16 * LDT * 2 + ko);
            #pragma unroll
            for (int mi = 0; mi < 4; mi++)
                #pragma unroll
                for (int ni = 0; ni < 3; ni++)
                    mma16816(acc[mi][ni], af[mi], bh[ni]);      // Ah*Bh
            #pragma unroll
            for (int ni = 0; ni < 3; ni++)
                ldm_x2(bl[ni], pBl + ni * 8 * LDT * 2 + ko);
            #pragma unroll
            for (int mi = 0; mi < 4; mi++)
                #pragma unroll
                for (int ni = 0; ni < 3; ni++)
                    mma16816(acc[mi][ni], af[mi], bl[ni]);      // Ah*Bl
            #pragma unroll
            for (int mi = 0; mi < 4; mi++)
                ldm_x4(af[mi], pAl + mi * 16 * LDT * 2 + ko);
            #pragma unroll
            for (int mi = 0; mi < 4; mi++)
                #pragma unroll
                for (int ni = 0; ni < 3; ni++)
                    mma16816(acc[mi][ni], af[mi], bh[ni]);      // Al*Bh
        }
        __syncthreads();
    }

    // epilogue
    const int erow = lane >> 2;
    const int ecol = (lane & 3) * 2;
    #pragma unroll
    for (int mi = 0; mi < 4; mi++) {
        #pragma unroll
        for (int ni = 0; ni < 3; ni++) {
            #pragma unroll
            for (int q = 0; q < 4; q++) {
                int gm = m0 + warp_m * 64 + mi * 16 + erow + (q >> 1) * 8;
                int gn = n0 + warp_n * 24 + ni * 8 + ecol + (q & 1);
                if (MODE == 0) {
                    if (gm < NROWS && gn < O_OUT) {
                        int b = gm / C_IN, c = gm - (gm / C_IN) * C_IN;
                        g_w[((size_t)b * O_OUT + gn) * C_IN + c] = acc[mi][ni][q];
                    }
                } else {
                    if (gm < T_LEN && gn < O_OUT)
                        outp[((size_t)bb * O_OUT + gn) * T_LEN + gm] = acc[mi][ni][q];
                }
            }
        }
    }
}

// ---------------------------------------------------------------- launch
extern "C" void kernel_launch(void* const* d_in, const int* in_sizes, int n_in,
                              void* d_out, int out_size) {
    const float* brain  = (const float*)d_in[0];   // [32, 273, 3000]
    const float* layout = (const float*)d_in[1];   // [32, 273, 2]
    const float* heads  = (const float*)d_in[2];   // [270, 2048]
    float* out = (float*)d_out;                    // [32, 270, 3000]

    cudaFuncSetAttribute(k_gemm_mma<0, KDIM / 32>,
                         cudaFuncAttributeMaxDynamicSharedMemorySize, SMEM_TOTAL);
    cudaFuncSetAttribute(k_gemm_mma<1, K2PAD / 32>,
                         cudaFuncAttributeMaxDynamicSharedMemorySize, SMEM_TOTAL);

    k_emb<<<NROWS / 8, 256>>>(layout);
    k_conv_heads<<<(O_OUT * KDIM + 255) / 256, 256>>>(heads);
    k_conv_brain<<<dim3(94, 9, B_SZ), dim3(32, 8)>>>(brain);

    k_gemm_mma<0, KDIM / 32><<<dim3(69, 3), 256, SMEM_TOTAL>>>(nullptr);     // scores

    k_softmax<<<(B_SZ * O_OUT + 7) / 8, 256>>>();

    k_gemm_mma<1, K2PAD / 32><<<dim3(24, 3, B_SZ), 256, SMEM_TOTAL>>>(out);  // output
}

// round 8
// speedup vs baseline: 2.8264x; 1.1549x over previous
#include <cuda_runtime.h>
#include <cuda_bf16.h>
#include <math.h>
#include <stdint.h>

// ---------------------------------------------------------------- constants
#define B_SZ   32
#define C_IN   273
#define T_LEN  3000
#define O_OUT  270
#define KDIM   2048
#define NROWS  (B_SZ * C_IN)   // 8736
#define EROWS  8960            // pad (>= 137*64)
#define ORPAD  288             // 3*96
#define TPAD   3072            // 24*128
#define K2PAD  288             // 9*32
#define LDT    40              // smem leading dim (bf16) -> 80B rows

// ---------------------------------------------------------------- scratch
__device__ float g_w[(size_t)B_SZ * O_OUT * C_IN];                 // scores fp32
__device__ __nv_bfloat16 g_Eh[(size_t)EROWS * KDIM];               // emb hi
__device__ __nv_bfloat16 g_El[(size_t)EROWS * KDIM];               // emb lo
__device__ __nv_bfloat16 g_Hh[(size_t)ORPAD * KDIM];               // heads hi
__device__ __nv_bfloat16 g_Hl[(size_t)ORPAD * KDIM];               // heads lo
__device__ __nv_bfloat16 g_Bth[(size_t)B_SZ * TPAD * K2PAD];       // brain^T hi [b][t][c]
__device__ __nv_bfloat16 g_Btl[(size_t)B_SZ * TPAD * K2PAD];       // brain^T lo
__device__ __nv_bfloat16 g_Wh[(size_t)B_SZ * ORPAD * K2PAD];       // weights hi [b][o][c]
__device__ __nv_bfloat16 g_Wl[(size_t)B_SZ * ORPAD * K2PAD];       // weights lo

// ---------------------------------------------------------------- helpers
__device__ __forceinline__ uint32_t smem_u32(const void* p) {
    uint32_t a;
    asm("{ .reg .u64 t; cvta.to.shared.u64 t, %1; cvt.u32.u64 %0, t; }" : "=r"(a) : "l"(p));
    return a;
}
__device__ __forceinline__ void cp_async16(uint32_t dst, const void* src) {
    asm volatile("cp.async.cg.shared.global [%0], [%1], 16;" :: "r"(dst), "l"(src));
}
#define CP_COMMIT() asm volatile("cp.async.commit_group;" ::: "memory")
#define CP_WAIT(n)  asm volatile("cp.async.wait_group %0;" :: "n"(n) : "memory")

__device__ __forceinline__ void ldm_x4(uint32_t* r, uint32_t addr) {
    asm volatile("ldmatrix.sync.aligned.m8n8.x4.shared.b16 {%0,%1,%2,%3}, [%4];"
        : "=r"(r[0]), "=r"(r[1]), "=r"(r[2]), "=r"(r[3]) : "r"(addr));
}
__device__ __forceinline__ void ldm_x2(uint32_t* r, uint32_t addr) {
    asm volatile("ldmatrix.sync.aligned.m8n8.x2.shared.b16 {%0,%1}, [%2];"
        : "=r"(r[0]), "=r"(r[1]) : "r"(addr));
}
__device__ __forceinline__ void mma16816(float* c, const uint32_t* a, const uint32_t* b) {
    asm volatile("mma.sync.aligned.m16n8k16.row.col.f32.bf16.bf16.f32 "
        "{%0,%1,%2,%3}, {%4,%5,%6,%7}, {%8,%9}, {%0,%1,%2,%3};"
        : "+f"(c[0]), "+f"(c[1]), "+f"(c[2]), "+f"(c[3])
        : "r"(a[0]), "r"(a[1]), "r"(a[2]), "r"(a[3]), "r"(b[0]), "r"(b[1]));
}
__device__ __forceinline__ void split_bf16(float v, __nv_bfloat16& h, __nv_bfloat16& l) {
    h = __float2bfloat16(v);
    l = __float2bfloat16(v - __bfloat162float(h));
}

// ---------------------------------------------------------------- fourier emb
__global__ void k_emb(const float* __restrict__ layout) {
    int warp = threadIdx.x >> 5, lane = threadIdx.x & 31;
    int row = blockIdx.x * 8 + warp;
    if (row >= NROWS) return;
    float x = layout[row * 2 + 0], y = layout[row * 2 + 1];
    const float TWO_PI = 6.283185307179586476f;
    float pa = TWO_PI * ((x + 0.1f) * (1.0f / 1.2f));
    float pb = TWO_PI * ((y + 0.1f) * (1.0f / 1.2f));
    float sa, ca, sb, cb;
    sincosf(pa * (float)lane, &sa, &ca);
    sincosf(pb * (float)lane, &sb, &cb);
    size_t base = (size_t)row * KDIM;
    #pragma unroll 4
    for (int i = 0; i < 32; i++) {
        float sai = __shfl_sync(0xffffffffu, sa, i);
        float cai = __shfl_sync(0xffffffffu, ca, i);
        float vs = fmaf(sai, cb,  cai * sb);
        float vc = fmaf(cai, cb, -sai * sb);
        __nv_bfloat16 h, l;
        split_bf16(vs, h, l);
        g_Eh[base + i * 32 + lane] = h;  g_El[base + i * 32 + lane] = l;
        split_bf16(vc, h, l);
        g_Eh[base + 1024 + i * 32 + lane] = h;  g_El[base + 1024 + i * 32 + lane] = l;
    }
}

// ---------------------------------------------------------------- conversions
__global__ void k_conv_heads(const float* __restrict__ heads) {
    int idx = blockIdx.x * 256 + threadIdx.x;
    if (idx >= O_OUT * KDIM) return;
    __nv_bfloat16 h, l;
    split_bf16(heads[idx], h, l);
    g_Hh[idx] = h; g_Hl[idx] = l;
}

__global__ void k_conv_brain(const float* __restrict__ brain) {
    __shared__ float tile[32][33];
    int b = blockIdx.z;
    int c0 = blockIdx.y * 32, t0 = blockIdx.x * 32;
    int tx = threadIdx.x, ty = threadIdx.y;   // block (32,8)
    const float* src = brain + (size_t)b * C_IN * T_LEN;
    #pragma unroll
    for (int u = 0; u < 4; u++) {
        int c = c0 + ty + u * 8, t = t0 + tx;
        tile[ty + u * 8][tx] = (c < C_IN && t < T_LEN) ? src[(size_t)c * T_LEN + t] : 0.f;
    }
    __syncthreads();
    #pragma unroll
    for (int u = 0; u < 4; u++) {
        int t = t0 + ty + u * 8, c = c0 + tx;   // padded bounds: t<3072, c<288
        __nv_bfloat16 h, l;
        split_bf16(tile[tx][ty + u * 8], h, l);
        size_t di = ((size_t)b * TPAD + t) * K2PAD + c;
        g_Bth[di] = h; g_Btl[di] = l;
    }
}

// ---------------------------------------------------------------- softmax (+ fused bf16 split)
__global__ void k_softmax() {
    int warp = threadIdx.x >> 5, lane = threadIdx.x & 31;
    int row = blockIdx.x * 8 + warp;
    if (row >= B_SZ * O_OUT) return;
    int b = row / O_OUT, o = row - b * O_OUT;
    const float* base = g_w + (size_t)row * C_IN;
    float v[9];
    float mx = -3.0e38f;
    #pragma unroll
    for (int it = 0; it < 9; it++) {
        int c = lane + it * 32;
        v[it] = (c < C_IN) ? base[c] : -3.0e38f;
        mx = fmaxf(mx, v[it]);
    }
    #pragma unroll
    for (int off = 16; off; off >>= 1)
        mx = fmaxf(mx, __shfl_xor_sync(0xffffffffu, mx, off));
    float s = 0.f;
    #pragma unroll
    for (int it = 0; it < 9; it++) {
        int c = lane + it * 32;
        float e = (c < C_IN) ? expf(v[it] - mx) : 0.f;
        v[it] = e; s += e;
    }
    #pragma unroll
    for (int off = 16; off; off >>= 1)
        s += __shfl_xor_sync(0xffffffffu, s, off);
    float inv = 1.f / s;
    __nv_bfloat16* wh = g_Wh + ((size_t)b * ORPAD + o) * K2PAD;
    __nv_bfloat16* wl = g_Wl + ((size_t)b * ORPAD + o) * K2PAD;
    #pragma unroll
    for (int it = 0; it < 9; it++) {
        int c = lane + it * 32;
        if (c < C_IN) {
            __nv_bfloat16 h, l;
            split_bf16(v[it] * inv, h, l);
            wh[c] = h; wl[c] = l;
        }
    }
}

// ---------------------------------------------------------------- GEMM
// Block BM(m) x 96(n), BK=32, 8 warps (2m x 4n), warp (BM/2)x24.
// split-bf16 3-MMA fp32 emulation. cp.async pipelined, one sync per chunk:
//   wait(S-2) -> syncthreads -> prefetch(kc+S-1) -> compute(kc)
// MODE 0: scores = emb x heads  -> g_w [b][o][c]   (BM=64, 3 CTAs/SM, S=2)
// MODE 1: out    = brainT x W   -> out [b][o][t]   (BM=128, 2 CTAs/SM, S=3)
template<int BM>
__device__ __forceinline__ void stage_loads(uint32_t sbase,
        const __nv_bfloat16* __restrict__ Ah, const __nv_bfloat16* __restrict__ Al, int lda,
        const __nv_bfloat16* __restrict__ Bh, const __nv_bfloat16* __restrict__ Bl, int ldb,
        int k0, int tid) {
    constexpr int SA = BM * LDT * 2;        // one A plane bytes
    constexpr int SB = 96 * LDT * 2;        // one B plane bytes
    #pragma unroll
    for (int u = 0; u < BM / 64; u++) {
        int idx = u * 256 + tid;
        int row = idx >> 2, seg = idx & 3;
        uint32_t d = sbase + (row * LDT + seg * 8) * 2;
        cp_async16(d,      Ah + (size_t)row * lda + k0 + seg * 8);
        cp_async16(d + SA, Al + (size_t)row * lda + k0 + seg * 8);
    }
    #pragma unroll
    for (int u = 0; u < 2; u++) {
        int idx = u * 256 + tid;
        if (idx < 384) {
            int row = idx >> 2, seg = idx & 3;
            uint32_t d = sbase + 2 * SA + (row * LDT + seg * 8) * 2;
            cp_async16(d,      Bh + (size_t)row * ldb + k0 + seg * 8);
            cp_async16(d + SB, Bl + (size_t)row * ldb + k0 + seg * 8);
        }
    }
}

template<int MODE, int BM, int STAGES, int KCHUNKS, int MINB>
__global__ __launch_bounds__(256, MINB) void k_gemm_mma(float* __restrict__ outp) {
    constexpr int MI = BM / 32;             // m16 tiles per warp
    constexpr int SA = BM * LDT * 2;
    constexpr int SB = 96 * LDT * 2;
    constexpr int STAGE = 2 * SA + 2 * SB;

    extern __shared__ __align__(16) char dsm[];
    const uint32_t sb = smem_u32(dsm);

    const int tid = threadIdx.x;
    const int lane = tid & 31, wid = tid >> 5;
    const int warp_m = wid >> 2, warp_n = wid & 3;

    const __nv_bfloat16 *Ah, *Al, *Bh, *Bl;
    int lda, ldb, m0, n0, bb = 0;
    if (MODE == 0) {
        m0 = blockIdx.x * BM;  n0 = blockIdx.y * 96;
        lda = KDIM; ldb = KDIM;
        Ah = g_Eh + (size_t)m0 * KDIM;  Al = g_El + (size_t)m0 * KDIM;
        Bh = g_Hh + (size_t)n0 * KDIM;  Bl = g_Hl + (size_t)n0 * KDIM;
    } else {
        bb = blockIdx.z;
        m0 = blockIdx.x * BM;  n0 = blockIdx.y * 96;
        lda = K2PAD; ldb = K2PAD;
        Ah = g_Bth + ((size_t)bb * TPAD + m0) * K2PAD;
        Al = g_Btl + ((size_t)bb * TPAD + m0) * K2PAD;
        Bh = g_Wh + ((size_t)bb * ORPAD + n0) * K2PAD;
        Bl = g_Wl + ((size_t)bb * ORPAD + n0) * K2PAD;
    }

    float acc[MI][3][4];
    #pragma unroll
    for (int i = 0; i < MI; i++)
        #pragma unroll
        for (int j = 0; j < 3; j++)
            #pragma unroll
            for (int q = 0; q < 4; q++) acc[i][j][q] = 0.f;

    const int a_row = warp_m * (BM / 2) + (lane & 15);
    const int a_col = (lane >> 4) * 8;
    const int b_row = warp_n * 24 + (lane & 7);
    const int b_col = ((lane >> 3) & 1) * 8;
    const uint32_t aoff = (a_row * LDT + a_col) * 2;
    const uint32_t boff = (b_row * LDT + b_col) * 2;

    // prologue: stages 0..S-2
    #pragma unroll
    for (int s = 0; s < STAGES - 1; s++) {
        stage_loads<BM>(sb + s * STAGE, Ah, Al, lda, Bh, Bl, ldb, s * 32, tid);
        CP_COMMIT();
    }

    int cstg = 0, pstg = STAGES - 1;
    for (int kc = 0; kc < KCHUNKS; kc++) {
        CP_WAIT(STAGES - 2);
        __syncthreads();
        // prefetch stage kc+S-1 (always commit to keep group count uniform)
        int pf = kc + STAGES - 1;
        if (pf < KCHUNKS)
            stage_loads<BM>(sb + pstg * STAGE, Ah, Al, lda, Bh, Bl, ldb, pf * 32, tid);
        CP_COMMIT();
        if (++pstg == STAGES) pstg = 0;

        const uint32_t stg = sb + cstg * STAGE;
        if (++cstg == STAGES) cstg = 0;

        const uint32_t pAh = stg + aoff;
        const uint32_t pAl = stg + SA + aoff;
        const uint32_t pBh = stg + 2 * SA + boff;
        const uint32_t pBl = stg + 2 * SA + SB + boff;
        #pragma unroll
        for (int ks = 0; ks < 2; ks++) {
            const uint32_t ko = ks * 32;   // 16 bf16 = 32 B
            uint32_t bh[3][2], bl[3][2], af[MI][4];
            #pragma unroll
            for (int ni = 0; ni < 3; ni++)
                ldm_x2(bh[ni], pBh + ni * 8 * LDT * 2 + ko);
            #pragma unroll
            for (int mi = 0; mi < MI; mi++)
                ldm_x4(af[mi], pAh + mi * 16 * LDT * 2 + ko);
            #pragma unroll
            for (int mi = 0; mi < MI; mi++)
                #pragma unroll
                for (int ni = 0; ni < 3; ni++)
                    mma16816(acc[mi][ni], af[mi], bh[ni]);      // Ah*Bh
            #pragma unroll
            for (int ni = 0; ni < 3; ni++)
                ldm_x2(bl[ni], pBl + ni * 8 * LDT * 2 + ko);
            #pragma unroll
            for (int mi = 0; mi < MI; mi++)
                #pragma unroll
                for (int ni = 0; ni < 3; ni++)
                    mma16816(acc[mi][ni], af[mi], bl[ni]);      // Ah*Bl
            #pragma unroll
            for (int mi = 0; mi < MI; mi++)
                ldm_x4(af[mi], pAl + mi * 16 * LDT * 2 + ko);
            #pragma unroll
            for (int mi = 0; mi < MI; mi++)
                #pragma unroll
                for (int ni = 0; ni < 3; ni++)
                    mma16816(acc[mi][ni], af[mi], bh[ni]);      // Al*Bh
        }
    }

    // epilogue
    const int erow = lane >> 2;
    const int ecol = (lane & 3) * 2;
    #pragma unroll
    for (int mi = 0; mi < MI; mi++) {
        #pragma unroll
        for (int ni = 0; ni < 3; ni++) {
            #pragma unroll
            for (int q = 0; q < 4; q++) {
                int gm = m0 + warp_m * (BM / 2) + mi * 16 + erow + (q >> 1) * 8;
                int gn = n0 + warp_n * 24 + ni * 8 + ecol + (q & 1);
                if (MODE == 0) {
                    if (gm < NROWS && gn < O_OUT) {
                        int b = gm / C_IN, c = gm - (gm / C_IN) * C_IN;
                        g_w[((size_t)b * O_OUT + gn) * C_IN + c] = acc[mi][ni][q];
                    }
                } else {
                    if (gm < T_LEN && gn < O_OUT)
                        outp[((size_t)bb * O_OUT + gn) * T_LEN + gm] = acc[mi][ni][q];
                }
            }
        }
    }
}

// ---------------------------------------------------------------- launch
extern "C" void kernel_launch(void* const* d_in, const int* in_sizes, int n_in,
                              void* d_out, int out_size) {
    const float* brain  = (const float*)d_in[0];   // [32, 273, 3000]
    const float* layout = (const float*)d_in[1];   // [32, 273, 2]
    const float* heads  = (const float*)d_in[2];   // [270, 2048]
    float* out = (float*)d_out;                    // [32, 270, 3000]

    // gemm1: BM=64, 2 stages, 3 CTAs/SM.  stage = 2*5120 + 2*7680 = 25600
    constexpr int SM1 = 2 * (2 * 64 * LDT * 2 + 2 * 96 * LDT * 2);   // 51200
    // gemm2: BM=128, 3 stages, 2 CTAs/SM. stage = 2*10240 + 2*7680 = 35840
    constexpr int SM2 = 3 * (2 * 128 * LDT * 2 + 2 * 96 * LDT * 2);  // 107520

    cudaFuncSetAttribute((const void*)k_gemm_mma<0, 64, 2, KDIM / 32, 3>,
                         cudaFuncAttributeMaxDynamicSharedMemorySize, SM1);
    cudaFuncSetAttribute((const void*)k_gemm_mma<1, 128, 3, K2PAD / 32, 2>,
                         cudaFuncAttributeMaxDynamicSharedMemorySize, SM2);

    k_emb<<<NROWS / 8, 256>>>(layout);
    k_conv_heads<<<(O_OUT * KDIM + 255) / 256, 256>>>(heads);
    k_conv_brain<<<dim3(94, 9, B_SZ), dim3(32, 8)>>>(brain);

    k_gemm_mma<0, 64, 2, KDIM / 32, 3>
        <<<dim3(137, 3), 256, SM1>>>(nullptr);                       // scores

    k_softmax<<<(B_SZ * O_OUT + 7) / 8, 256>>>();

    k_gemm_mma<1, 128, 3, K2PAD / 32, 2>
        <<<dim3(24, 3, B_SZ), 256, SM2>>>(out);                      // output
}